// round 5
// baseline (speedup 1.0000x reference)
#include <cuda_runtime.h>
#include <cuda_bf16.h>
#include <cstdint>

using bf16 = __nv_bfloat16;
constexpr int NTK = 16384, DIMD = 1024, HIDH = 2048;

// ---------------- fp32 scratch ----------------
__device__ float g_kf[(size_t)NTK * DIMD], g_vf[(size_t)NTK * DIMD], g_ef[(size_t)NTK * DIMD];
__device__ float g_zf[(size_t)NTK * HIDH], g_hf[(size_t)NTK * HIDH], g_dzf[(size_t)NTK * HIDH];
__device__ float g_P1[8ull * HIDH * DIMD], g_P2[8ull * DIMD * HIDH];
__device__ float g_part[3 * 1024], g_scal[3];
// ---------------- bf16 hi/lo panels ----------------
__device__ bf16 px_h[(size_t)NTK * DIMD],  px_l[(size_t)NTK * DIMD];
__device__ bf16 pk_h[(size_t)NTK * DIMD],  pk_l[(size_t)NTK * DIMD];
__device__ bf16 pq_h[(size_t)NTK * DIMD],  pq_l[(size_t)NTK * DIMD];
__device__ bf16 pe_h[(size_t)NTK * DIMD],  pe_l[(size_t)NTK * DIMD];
__device__ bf16 ph_h[(size_t)NTK * HIDH],  ph_l[(size_t)NTK * HIDH];
__device__ bf16 pkT_h[(size_t)NTK * DIMD], pkT_l[(size_t)NTK * DIMD];
__device__ bf16 peT_h[(size_t)NTK * DIMD], peT_l[(size_t)NTK * DIMD];
__device__ bf16 phT_h[(size_t)NTK * HIDH], phT_l[(size_t)NTK * HIDH];
__device__ bf16 pdzT_h[(size_t)NTK * HIDH], pdzT_l[(size_t)NTK * HIDH];
__device__ bf16 pW_h[7][DIMD * DIMD], pW_l[7][DIMD * DIMD];
__device__ bf16 pM1_h[HIDH * DIMD],  pM1_l[HIDH * DIMD];
__device__ bf16 pM2_h[DIMD * HIDH],  pM2_l[DIMD * HIDH];
__device__ bf16 pM2T_h[HIDH * DIMD], pM2T_l[HIDH * DIMD];
__device__ bf16 pM1n_h[HIDH * DIMD], pM1n_l[HIDH * DIMD];
__device__ bf16 pM2n_h[DIMD * HIDH], pM2n_l[DIMD * HIDH];

// ---------------- asm helpers ----------------
__device__ __forceinline__ uint32_t s2u(const void* p) {
  uint32_t a;
  asm("{ .reg .u64 t; cvta.to.shared.u64 t, %1; cvt.u32.u64 %0, t; }" : "=r"(a) : "l"(p));
  return a;
}
#define CP16(d, s) asm volatile("cp.async.cg.shared.global [%0],[%1],16;" :: "r"(d), "l"(s))
#define CPC()  asm volatile("cp.async.commit_group;")
#define CPW1() asm volatile("cp.async.wait_group 1;")
#define CPW0() asm volatile("cp.async.wait_group 0;")

__device__ __forceinline__ void ldsm4(uint32_t* r, uint32_t a) {
  asm volatile("ldmatrix.sync.aligned.m8n8.x4.shared.b16 {%0,%1,%2,%3},[%4];"
               : "=r"(r[0]), "=r"(r[1]), "=r"(r[2]), "=r"(r[3]) : "r"(a));
}
__device__ __forceinline__ void mma_(float* c, const uint32_t* a, const uint32_t* b) {
  asm volatile("mma.sync.aligned.m16n8k16.row.col.f32.bf16.bf16.f32 "
               "{%0,%1,%2,%3},{%4,%5,%6,%7},{%8,%9},{%0,%1,%2,%3};"
               : "+f"(c[0]), "+f"(c[1]), "+f"(c[2]), "+f"(c[3])
               : "r"(a[0]), "r"(a[1]), "r"(a[2]), "r"(a[3]), "r"(b[0]), "r"(b[1]));
}
__device__ __forceinline__ uint32_t packbf(float x, float y) {
  __nv_bfloat162 t = __floats2bfloat162_rn(x, y);
  return *(uint32_t*)&t;
}
__device__ __forceinline__ void wpanel(bf16* Ph, bf16* Pl, size_t ix, float x, float y) {
  float hx = __bfloat162float(__float2bfloat16(x));
  float hy = __bfloat162float(__float2bfloat16(y));
  *(uint32_t*)(Ph + ix) = packbf(hx, hy);
  *(uint32_t*)(Pl + ix) = packbf(x - hx, y - hy);
}
__device__ __forceinline__ float sigf(float x) { return 1.f / (1.f + __expf(-x)); }

// ---------------- GEMM: C[128x256] = A(MxK) @ B(NxK)^T, NP-split bf16 ----------------
// smem stage: [AH 10240][AL 10240][BH 20480][BL 20480] = 61440 B, 2 stages.
// EPI: 0 store  1 silu(Cz=pre,C=silu)  2 scale*(v-X1)  3 v*silu'(X1)  5 gate-mean
constexpr int SMST = 61440, SMTOT = 122880;

template<int EPI, int NP>
__global__ void __launch_bounds__(256, 1)
tc(const bf16* __restrict__ Ah, const bf16* __restrict__ Al,
   const bf16* __restrict__ Bh, const bf16* __restrict__ Bl,
   int lda, int ldb, int nK,
   float* C, float* Cz, bf16* Ph, bf16* Pl, int ldc,
   const float* __restrict__ X1, const float* __restrict__ bias,
   float* partial, float scale)
{
  extern __shared__ __align__(16) char sm[];
  const int tid = threadIdx.x, wid = tid >> 5, lane = tid & 31;
  const size_t m0 = (size_t)blockIdx.y * 128, n0 = (size_t)blockIdx.x * 256;
  const size_t kpos = (size_t)blockIdx.z * nK * 32;
  if (C) C += (size_t)blockIdx.z * gridDim.y * 128 * ldc;
  const uint32_t sb = s2u(sm);
  const int m_w = (wid >> 2) * 64, n_w = (wid & 3) * 64;

  auto loadst = [&](int st, int kc) {
    size_t ao = m0 * lda + kpos + (size_t)kc * 32;
    size_t bo = n0 * ldb + kpos + (size_t)kc * 32;
    uint32_t d = sb + st * SMST;
#pragma unroll
    for (int i = 0; i < 2; ++i) {                 // A: 128 rows
      int idx = tid * 2 + i, row = idx >> 2, c16 = idx & 3;
      uint32_t doff = row * 80 + c16 * 16;
      size_t sa = ao + (size_t)row * lda + c16 * 8;
      CP16(d + doff, Ah + sa);
      if (NP == 3) CP16(d + 10240 + doff, Al + sa);
    }
#pragma unroll
    for (int i = 0; i < 4; ++i) {                 // B: 256 rows
      int idx = tid * 4 + i, row = idx >> 2, c16 = idx & 3;
      uint32_t doff = row * 80 + c16 * 16;
      size_t sB = bo + (size_t)row * ldb + c16 * 8;
      CP16(d + 20480 + doff, Bh + sB);
      if (NP == 3) CP16(d + 40960 + doff, Bl + sB);
    }
  };

  float acc[4][8][4] = {};
  loadst(0, 0); CPC();
  for (int kc = 0; kc < nK; ++kc) {
    if (kc + 1 < nK) { loadst((kc + 1) & 1, kc + 1); CPC(); CPW1(); }
    else CPW0();
    __syncthreads();
    uint32_t base = sb + (kc & 1) * SMST;
#pragma unroll
    for (int k2 = 0; k2 < 2; ++k2) {
      uint32_t aH[4][4], aL[4][4], bF[8][2], t4[4];
      uint32_t aRow = base + (m_w + (lane & 15)) * 80 + (lane >> 4) * 16 + k2 * 32;
      uint32_t bRow = base + 20480 + (n_w + (lane & 7) + ((lane >> 4) << 3)) * 80
                    + ((lane >> 3) & 1) * 16 + k2 * 32;
#pragma unroll
      for (int mt = 0; mt < 4; ++mt) ldsm4(aH[mt], aRow + mt * 1280);
      if (NP == 3) {
#pragma unroll
        for (int mt = 0; mt < 4; ++mt) ldsm4(aL[mt], aRow + 10240 + mt * 1280);
      }
#pragma unroll
      for (int np = 0; np < 4; ++np) {            // Bh fragments (64 n-cols)
        ldsm4(t4, bRow + np * 1280);
        bF[np*2][0] = t4[0]; bF[np*2][1] = t4[1];
        bF[np*2+1][0] = t4[2]; bF[np*2+1][1] = t4[3];
      }
#pragma unroll
      for (int mt = 0; mt < 4; ++mt)
#pragma unroll
        for (int nt = 0; nt < 8; ++nt) mma_(acc[mt][nt], aH[mt], bF[nt]);   // Ah*Bh
      if (NP == 3) {
#pragma unroll
        for (int mt = 0; mt < 4; ++mt)
#pragma unroll
          for (int nt = 0; nt < 8; ++nt) mma_(acc[mt][nt], aL[mt], bF[nt]); // Al*Bh
#pragma unroll
        for (int np = 0; np < 4; ++np) {          // Bl overwrites bF
          ldsm4(t4, bRow + 20480 + np * 1280);
          bF[np*2][0] = t4[0]; bF[np*2][1] = t4[1];
          bF[np*2+1][0] = t4[2]; bF[np*2+1][1] = t4[3];
        }
#pragma unroll
        for (int mt = 0; mt < 4; ++mt)
#pragma unroll
          for (int nt = 0; nt < 8; ++nt) mma_(acc[mt][nt], aH[mt], bF[nt]); // Ah*Bl
      }
    }
    __syncthreads();
  }

  // ---- epilogue ----
  if (EPI == 5) {
    float s = 0.f;
#pragma unroll
    for (int mt = 0; mt < 4; ++mt)
#pragma unroll
      for (int nt = 0; nt < 8; ++nt) {
        size_t cg = n0 + n_w + nt * 8 + ((lane & 3) << 1);
        float b0 = __ldg(bias + cg), b1 = __ldg(bias + cg + 1);
        float* ac = acc[mt][nt];
        s += sigf(ac[0] + b0) + sigf(ac[1] + b1) + sigf(ac[2] + b0) + sigf(ac[3] + b1);
      }
    float* red = (float*)sm;
    red[tid] = s; __syncthreads();
    for (int o = 128; o > 0; o >>= 1) {
      if (tid < o) red[tid] += red[tid + o];
      __syncthreads();
    }
    if (tid == 0) partial[blockIdx.y * gridDim.x + blockIdx.x] = red[0];
    return;
  }
#pragma unroll
  for (int mt = 0; mt < 4; ++mt)
#pragma unroll
    for (int nt = 0; nt < 8; ++nt) {
      size_t rg = m0 + m_w + mt * 16 + (lane >> 2);
      size_t cg = n0 + n_w + nt * 8 + ((lane & 3) << 1);
      float* ac = acc[mt][nt];
#pragma unroll
      for (int h2 = 0; h2 < 2; ++h2) {
        size_t ix = (rg + h2 * 8) * (size_t)ldc + cg;
        float v0 = ac[h2 * 2], v1 = ac[h2 * 2 + 1];
        if (EPI == 1) {
          if (Cz) *(float2*)(Cz + ix) = make_float2(v0, v1);
          v0 = v0 * sigf(v0); v1 = v1 * sigf(v1);
        } else if (EPI == 2) {
          float2 vv = *(const float2*)(X1 + ix);
          v0 = scale * (v0 - vv.x); v1 = scale * (v1 - vv.y);
        } else if (EPI == 3) {
          float2 zz = *(const float2*)(X1 + ix);
          float s0 = sigf(zz.x), s1 = sigf(zz.y);
          v0 *= s0 * (1.f + zz.x * (1.f - s0));
          v1 *= s1 * (1.f + zz.y * (1.f - s1));
        }
        if (C) *(float2*)(C + ix) = make_float2(v0, v1);
        if (Ph) wpanel(Ph, Pl, ix, v0, v1);
      }
    }
}

// ---------------- split: fp32 -> bf16 hi/lo (same layout) ----------------
__global__ void k_split(const float* __restrict__ src, bf16* __restrict__ hi,
                        bf16* __restrict__ lo, size_t n8)
{
  for (size_t t = (size_t)blockIdx.x * blockDim.x + threadIdx.x; t < n8;
       t += (size_t)gridDim.x * blockDim.x) {
    size_t i = t * 8;
    float4 a = *(const float4*)(src + i), b = *(const float4*)(src + i + 4);
    float v[8] = {a.x, a.y, a.z, a.w, b.x, b.y, b.z, b.w};
    uint32_t H[4], L[4];
#pragma unroll
    for (int j = 0; j < 4; ++j) {
      float h0 = __bfloat162float(__float2bfloat16(v[2*j]));
      float h1 = __bfloat162float(__float2bfloat16(v[2*j+1]));
      H[j] = packbf(h0, h1); L[j] = packbf(v[2*j] - h0, v[2*j+1] - h1);
    }
    *(uint4*)(hi + i) = *(uint4*)H;
    *(uint4*)(lo + i) = *(uint4*)L;
  }
}

// transpose-split: fp32 src [R x C] -> bf16 hi/lo [C x R]
__global__ void k_split_t(const float* __restrict__ src, bf16* __restrict__ hi,
                          bf16* __restrict__ lo, int R, int C)
{
  __shared__ float tile[64][65];
  const int tid = threadIdx.x;
  const size_t r0 = (size_t)blockIdx.y * 64, c0 = (size_t)blockIdx.x * 64;
  const int lr = tid >> 4, lc = (tid & 15) << 2;
#pragma unroll
  for (int i = 0; i < 4; ++i) {
    int rr = lr + i * 16;
    float4 v = *(const float4*)(src + (r0 + rr) * C + c0 + lc);
    tile[rr][lc] = v.x; tile[rr][lc+1] = v.y; tile[rr][lc+2] = v.z; tile[rr][lc+3] = v.w;
  }
  __syncthreads();
#pragma unroll
  for (int p = 0; p < 2; ++p) {
    int task = tid + p * 256;
    int rpl = task >> 3, kl = (task & 7) << 3;
    uint32_t H[4], L[4];
#pragma unroll
    for (int j = 0; j < 4; ++j) {
      float x = tile[kl + 2*j][rpl], y = tile[kl + 2*j + 1][rpl];
      float hx = __bfloat162float(__float2bfloat16(x));
      float hy = __bfloat162float(__float2bfloat16(y));
      H[j] = packbf(hx, hy); L[j] = packbf(x - hx, y - hy);
    }
    size_t off = (c0 + rpl) * (size_t)R + r0 + kl;
    *(uint4*)(hi + off) = *(uint4*)H;
    *(uint4*)(lo + off) = *(uint4*)L;
  }
}

// combine 8 split-K partials + momentum/decay update -> bf16 panels
__global__ void k_upd(const float* __restrict__ P, const float* __restrict__ M,
                      const float* __restrict__ S, bf16* __restrict__ hi,
                      bf16* __restrict__ lo, size_t n8, size_t half)
{
  float al = g_scal[0], th = g_scal[1], et = g_scal[2];
  for (size_t t = (size_t)blockIdx.x * blockDim.x + threadIdx.x; t < n8;
       t += (size_t)gridDim.x * blockDim.x) {
    size_t i = t * 8;
    uint32_t H[4], L[4];
#pragma unroll
    for (int j = 0; j < 4; ++j) {
      size_t i0 = i + 2*j, i1 = i0 + 1;
      float gx = 0.f, gy = 0.f;
#pragma unroll
      for (int s = 0; s < 8; ++s) { gx += P[s * half + i0]; gy += P[s * half + i1]; }
      float x = (1.f - al) * M[i0] + et * S[i0] - th * gx;
      float y = (1.f - al) * M[i1] + et * S[i1] - th * gy;
      float hx = __bfloat162float(__float2bfloat16(x));
      float hy = __bfloat162float(__float2bfloat16(y));
      H[j] = packbf(hx, hy); L[j] = packbf(x - hx, y - hy);
    }
    *(uint4*)(hi + i) = *(uint4*)H;
    *(uint4*)(lo + i) = *(uint4*)L;
  }
}

__global__ void __launch_bounds__(256) k_fin()
{
  __shared__ float red[256];
  for (int g = 0; g < 3; ++g) {
    float s = 0.f;
    for (int i = threadIdx.x; i < 512; i += 256) s += g_part[g * 1024 + i];
    red[threadIdx.x] = s; __syncthreads();
    for (int o = 128; o > 0; o >>= 1) {
      if (threadIdx.x < o) red[threadIdx.x] += red[threadIdx.x + o];
      __syncthreads();
    }
    if (threadIdx.x == 0) g_scal[g] = red[0] * (1.f / ((float)NTK * (float)DIMD));
    __syncthreads();
  }
}

// ---------------- host ----------------
template<class T> static float* df(T& s) { void* p = 0; cudaGetSymbolAddress(&p, s); return (float*)p; }
template<class T> static bf16*  db(T& s) { void* p = 0; cudaGetSymbolAddress(&p, s); return (bf16*)p; }

extern "C" void kernel_launch(void* const* d_in, const int* in_sizes, int n_in,
                              void* d_out, int out_size)
{
  (void)in_sizes; (void)n_in; (void)out_size;
  const float* x = (const float*)d_in[0];
  const float* Ws[7] = {(const float*)d_in[1], (const float*)d_in[2], (const float*)d_in[3],
                        (const float*)d_in[4], (const float*)d_in[5], (const float*)d_in[7],
                        (const float*)d_in[9]}; // Wk Wv Wq Wout Wgd Wgl Wgm
  const float* bias[3] = {(const float*)d_in[6], (const float*)d_in[8], (const float*)d_in[10]};
  const float* M1 = (const float*)d_in[11];
  const float* M2 = (const float*)d_in[12];
  const float* S1 = (const float*)d_in[13];
  const float* S2 = (const float*)d_in[14];

  float *kf = df(g_kf), *vf = df(g_vf), *ef = df(g_ef);
  float *zf = df(g_zf), *hf = df(g_hf), *dzf = df(g_dzf);
  float *P1 = df(g_P1), *P2 = df(g_P2), *part = df(g_part);
  bf16 *pxh = db(px_h), *pxl = db(px_l), *pkh = db(pk_h), *pkl = db(pk_l);
  bf16 *pqh = db(pq_h), *pql = db(pq_l), *peh = db(pe_h), *pel = db(pe_l);
  bf16 *phh = db(ph_h), *phl = db(ph_l);
  bf16 *pkTh = db(pkT_h), *pkTl = db(pkT_l), *peTh = db(peT_h), *peTl = db(peT_l);
  bf16 *phTh = db(phT_h), *phTl = db(phT_l), *pdzTh = db(pdzT_h), *pdzTl = db(pdzT_l);
  bf16 *pWh = db(pW_h), *pWl = db(pW_l);
  bf16 *pM1h = db(pM1_h), *pM1l = db(pM1_l), *pM2h = db(pM2_h), *pM2l = db(pM2_l);
  bf16 *pM2Th = db(pM2T_h), *pM2Tl = db(pM2T_l);
  bf16 *pM1nh = db(pM1n_h), *pM1nl = db(pM1n_l), *pM2nh = db(pM2n_h), *pM2nl = db(pM2n_l);

  cudaFuncSetAttribute(tc<0,3>, cudaFuncAttributeMaxDynamicSharedMemorySize, SMTOT);
  cudaFuncSetAttribute(tc<1,3>, cudaFuncAttributeMaxDynamicSharedMemorySize, SMTOT);
  cudaFuncSetAttribute(tc<2,3>, cudaFuncAttributeMaxDynamicSharedMemorySize, SMTOT);
  cudaFuncSetAttribute(tc<3,3>, cudaFuncAttributeMaxDynamicSharedMemorySize, SMTOT);
  cudaFuncSetAttribute(tc<5,1>, cudaFuncAttributeMaxDynamicSharedMemorySize, SMTOT);

  const int T = 256;
  float* nf = nullptr; bf16* nb = nullptr;
  const size_t WDD = (size_t)DIMD * DIMD;
  dim3 gP(4, 128), gH(8, 128);

  // input splits
  k_split<<<2048, T>>>(x, pxh, pxl, (size_t)NTK * DIMD / 8);
  for (int i = 0; i < 7; ++i)
    k_split<<<512, T>>>(Ws[i], pWh + i * WDD, pWl + i * WDD, WDD / 8);
  k_split<<<512, T>>>(M1, pM1h, pM1l, (size_t)HIDH * DIMD / 8);
  k_split<<<512, T>>>(M2, pM2h, pM2l, (size_t)DIMD * HIDH / 8);
  k_split_t<<<dim3(HIDH / 64, DIMD / 64), T>>>(M2, pM2Th, pM2Tl, DIMD, HIDH);

  // projections (k also emits panels)
  tc<0,3><<<gP, T, SMTOT>>>(pxh, pxl, pWh + 0 * WDD, pWl + 0 * WDD, DIMD, DIMD, 32,
                            kf, nf, pkh, pkl, DIMD, nf, nf, nf, 0.f);
  tc<0,3><<<gP, T, SMTOT>>>(pxh, pxl, pWh + 1 * WDD, pWl + 1 * WDD, DIMD, DIMD, 32,
                            vf, nf, nb, nb, DIMD, nf, nf, nf, 0.f);
  tc<0,3><<<gP, T, SMTOT>>>(pxh, pxl, pWh + 2 * WDD, pWl + 2 * WDD, DIMD, DIMD, 32,
                            nf, nf, pqh, pql, DIMD, nf, nf, nf, 0.f);
  // gates: single-pass bf16 (scalar mean -> error ~1e-5, harmless)
  for (int g = 0; g < 3; ++g)
    tc<5,1><<<gP, T, SMTOT>>>(pxh, pxl, pWh + (4 + g) * WDD, pWl + (4 + g) * WDD,
                              DIMD, DIMD, 32, nf, nf, nb, nb, DIMD,
                              nf, bias[g], part + g * 1024, 0.f);
  k_fin<<<1, T>>>();
  k_split_t<<<dim3(DIMD / 64, NTK / 64), T>>>(kf, pkTh, pkTl, NTK, DIMD);

  // z = k @ M1^T, h = silu(z)
  tc<1,3><<<gH, T, SMTOT>>>(pkh, pkl, pM1h, pM1l, DIMD, DIMD, 32,
                            hf, zf, phh, phl, HIDH, nf, nf, nf, 0.f);
  k_split_t<<<dim3(HIDH / 64, NTK / 64), T>>>(hf, phTh, phTl, NTK, HIDH);

  // e = (2/D)(h @ M2^T - v)
  tc<2,3><<<gP, T, SMTOT>>>(phh, phl, pM2h, pM2l, HIDH, HIDH, 64,
                            ef, nf, peh, pel, DIMD, vf, nf, nf, 2.f / (float)DIMD);
  k_split_t<<<dim3(DIMD / 64, NTK / 64), T>>>(ef, peTh, peTl, NTK, DIMD);

  // dz = (e @ M2) * silu'(z)
  tc<3,3><<<gH, T, SMTOT>>>(peh, pel, pM2Th, pM2Tl, DIMD, DIMD, 32,
                            dzf, nf, nb, nb, HIDH, zf, nf, nf, 0.f);
  k_split_t<<<dim3(HIDH / 64, NTK / 64), T>>>(dzf, pdzTh, pdzTl, NTK, HIDH);

  // weight-grad GEMMs (split-K=8) + fused update into panels
  tc<0,3><<<dim3(4, 16, 8), T, SMTOT>>>(pdzTh, pdzTl, pkTh, pkTl, NTK, NTK, 64,
                                        P1, nf, nb, nb, DIMD, nf, nf, nf, 0.f);
  tc<0,3><<<dim3(8, 8, 8), T, SMTOT>>>(peTh, peTl, phTh, phTl, NTK, NTK, 64,
                                       P2, nf, nb, nb, HIDH, nf, nf, nf, 0.f);
  k_upd<<<512, T>>>(P1, M1, S1, pM1nh, pM1nl, (size_t)HIDH * DIMD / 8, (size_t)HIDH * DIMD);
  k_upd<<<512, T>>>(P2, M2, S2, pM2nh, pM2nl, (size_t)DIMD * HIDH / 8, (size_t)DIMD * HIDH);

  // retrieval
  tc<1,3><<<gH, T, SMTOT>>>(pqh, pql, pM1nh, pM1nl, DIMD, DIMD, 32,
                            nf, nf, phh, phl, HIDH, nf, nf, nf, 0.f);
  tc<0,3><<<gP, T, SMTOT>>>(phh, phl, pM2nh, pM2nl, HIDH, HIDH, 64,
                            nf, nf, peh, pel, DIMD, nf, nf, nf, 0.f);
  tc<0,3><<<gP, T, SMTOT>>>(peh, pel, pWh + 3 * WDD, pWl + 3 * WDD, DIMD, DIMD, 32,
                            (float*)d_out, nf, nb, nb, DIMD, nf, nf, nf, 0.f);
}